// round 3
// baseline (speedup 1.0000x reference)
#include <cuda_runtime.h>
#include <math.h>

// Problem constants
#define BB 4
#define NN 1024
#define RR 16
#define DE 128
#define DR 64
#define NBASE 192
#define OD 128
#define FR (DE + DR)            // 192 features per relation
#define FF (FR * RR)            // 3072 total features
#define RSPLIT 4
#define RG (RR / RSPLIT)        // 4 relations per main-kernel CTA

// Scratch (device globals: allocation-free per harness rules)
__device__ float g_WnT[RR * DE * OD];                       // 1 MB   W node-part, [r][d][o]
__device__ float g_WrT[RR * DR * OD];                       // 0.5 MB W rel-part,  [r][e][o]
__device__ float g_c[BB * RR * OD];                         // 32 KB  per-(b,r) relation constant
__device__ float g_Q[(size_t)BB * RR * NN * OD];            // 32 MB  Q'[b][r][j][o]
__device__ float g_part[(size_t)RSPLIT * BB * NN * OD];     // 8 MB   partial sums per r-split

// ---------------------------------------------------------------------------
// Kernel 1: W = Ww @ Wb, stored transposed & split into node/rel slices.
// grid (FF/256=12, OD/8=16), block 256
// ---------------------------------------------------------------------------
__global__ void k_W(const float* __restrict__ Wb, const float* __restrict__ Ww) {
    __shared__ float sWw[8][NBASE];
    int tx = threadIdx.x;
    int f  = blockIdx.x * 256 + tx;        // feature column 0..3071
    int o0 = blockIdx.y * 8;               // 8 output rows per block
    for (int i = tx; i < 8 * NBASE; i += 256)
        sWw[i / NBASE][i % NBASE] = Ww[(o0 + i / NBASE) * NBASE + (i % NBASE)];
    __syncthreads();
    float acc[8];
#pragma unroll
    for (int oo = 0; oo < 8; oo++) acc[oo] = 0.f;
    for (int m = 0; m < NBASE; m++) {
        float wb = Wb[m * FF + f];
#pragma unroll
        for (int oo = 0; oo < 8; oo++) acc[oo] = fmaf(sWw[oo][m], wb, acc[oo]);
    }
    int r = f / FR, d = f % FR;
    if (d < DE) {
#pragma unroll
        for (int oo = 0; oo < 8; oo++) g_WnT[(r * DE + d) * OD + o0 + oo] = acc[oo];
    } else {
        int e = d - DE;
#pragma unroll
        for (int oo = 0; oo < 8; oo++) g_WrT[(r * DR + e) * OD + o0 + oo] = acc[oo];
    }
}

// ---------------------------------------------------------------------------
// Kernel 2: c[b,r,o] = sum_e rel[b,r,e] * WrT[r][e][o]
// grid (BB*RR=64), block OD=128
// ---------------------------------------------------------------------------
__global__ void k_c(const float* __restrict__ rel) {
    int br = blockIdx.x;
    int r  = br % RR;
    int o  = threadIdx.x;
    float s = 0.f;
    const float* rp = rel + br * DR;
    const float* wp = g_WrT + r * DR * OD + o;
#pragma unroll 8
    for (int e = 0; e < DR; e++) s = fmaf(rp[e], wp[e * OD], s);
    g_c[br * OD + o] = s;
}

// ---------------------------------------------------------------------------
// Kernel 3: Q'[b,r,j,o] = (node_b @ WnT_r)[j,o] + c[b,r,o]
// 64x128 output tile, K=DE=128, BK=16. grid (NN/64=16, BB*RR=64), block 256
// ---------------------------------------------------------------------------
__global__ void __launch_bounds__(256, 2) k_Q(const float* __restrict__ node) {
    __shared__ float As[16][68];    // [k][j], padded to avoid bank conflicts
    __shared__ float Bs[16][128];   // [k][o]
    int tx = threadIdx.x;
    int tr = tx >> 4;               // 0..15 -> 4 rows each
    int tc = tx & 15;               // 0..15 -> 8 cols each
    int j0 = blockIdx.x * 64;
    int br = blockIdx.y;
    int b = br / RR, r = br % RR;
    int arow = tx >> 2;             // 0..63
    int aq   = tx & 3;              // 0..3

    const float* nodeBase = node + ((size_t)b * NN + j0) * DE;
    const float* wBase    = g_WnT + (size_t)r * DE * OD;

    float acc[4][8];
#pragma unroll
    for (int u = 0; u < 4; u++)
#pragma unroll
        for (int v = 0; v < 8; v++) acc[u][v] = 0.f;

    for (int d0 = 0; d0 < DE; d0 += 16) {
        float4 av  = *(const float4*)(nodeBase + (size_t)arow * DE + d0 + aq * 4);
        int k1 = tx >> 5, og = tx & 31;
        float4 bv0 = *(const float4*)(wBase + (size_t)(d0 + k1)     * OD + og * 4);
        float4 bv1 = *(const float4*)(wBase + (size_t)(d0 + k1 + 8) * OD + og * 4);
        __syncthreads();
        As[aq * 4 + 0][arow] = av.x;
        As[aq * 4 + 1][arow] = av.y;
        As[aq * 4 + 2][arow] = av.z;
        As[aq * 4 + 3][arow] = av.w;
        *(float4*)&Bs[k1][og * 4]     = bv0;
        *(float4*)&Bs[k1 + 8][og * 4] = bv1;
        __syncthreads();
#pragma unroll
        for (int k = 0; k < 16; k++) {
            float4 a  = *(const float4*)&As[k][tr * 4];
            float4 b0 = *(const float4*)&Bs[k][tc * 8];
            float4 b1 = *(const float4*)&Bs[k][tc * 8 + 4];
            float ar[4] = {a.x, a.y, a.z, a.w};
            float brv[8] = {b0.x, b0.y, b0.z, b0.w, b1.x, b1.y, b1.z, b1.w};
#pragma unroll
            for (int u = 0; u < 4; u++)
#pragma unroll
                for (int v = 0; v < 8; v++) acc[u][v] = fmaf(ar[u], brv[v], acc[u][v]);
        }
    }
    // add relation constant c[b,r,o] (constant over j), store Q'
    float4 c0 = *(const float4*)(g_c + br * OD + tc * 8);
    float4 c1 = *(const float4*)(g_c + br * OD + tc * 8 + 4);
    float cv[8] = {c0.x, c0.y, c0.z, c0.w, c1.x, c1.y, c1.z, c1.w};
    float* qp = g_Q + ((size_t)br * NN + j0 + tr * 4) * OD + tc * 8;
#pragma unroll
    for (int u = 0; u < 4; u++) {
        float4 s0, s1;
        s0.x = acc[u][0] + cv[0]; s0.y = acc[u][1] + cv[1];
        s0.z = acc[u][2] + cv[2]; s0.w = acc[u][3] + cv[3];
        s1.x = acc[u][4] + cv[4]; s1.y = acc[u][5] + cv[5];
        s1.z = acc[u][6] + cv[6]; s1.w = acc[u][7] + cv[7];
        *(float4*)(qp + (size_t)u * OD)     = s0;
        *(float4*)(qp + (size_t)u * OD + 4) = s1;
    }
}

// ---------------------------------------------------------------------------
// Kernel 4: main GEMM. part[rs][b,i,o] = sum_{r in group rs} sum_j adj[b,r,i,j]*Q'[b,r,j,o]
// 64x128 output tile, K = RG*NN = 4096, BK=16. grid (16, BB, RSPLIT), block 256
// ---------------------------------------------------------------------------
__global__ void __launch_bounds__(256, 2) k_main(const float* __restrict__ adj) {
    __shared__ float As[16][68];
    __shared__ float Bs[16][128];
    int tx = threadIdx.x;
    int tr = tx >> 4;
    int tc = tx & 15;
    int i0 = blockIdx.x * 64;
    int b  = blockIdx.y;
    int rs = blockIdx.z;
    int arow = tx >> 2;
    int aq   = tx & 3;
    int k1 = tx >> 5, og = tx & 31;

    float acc[4][8];
#pragma unroll
    for (int u = 0; u < 4; u++)
#pragma unroll
        for (int v = 0; v < 8; v++) acc[u][v] = 0.f;

    for (int rr = 0; rr < RG; rr++) {
        int r = rs * RG + rr;
        const float* adjBase = adj + ((size_t)(b * RR + r) * NN + i0) * NN;
        const float* qBase   = g_Q + (size_t)(b * RR + r) * NN * OD;
        for (int j0 = 0; j0 < NN; j0 += 16) {
            float4 av  = *(const float4*)(adjBase + (size_t)arow * NN + j0 + aq * 4);
            float4 bv0 = *(const float4*)(qBase + (size_t)(j0 + k1)     * OD + og * 4);
            float4 bv1 = *(const float4*)(qBase + (size_t)(j0 + k1 + 8) * OD + og * 4);
            __syncthreads();
            As[aq * 4 + 0][arow] = av.x;
            As[aq * 4 + 1][arow] = av.y;
            As[aq * 4 + 2][arow] = av.z;
            As[aq * 4 + 3][arow] = av.w;
            *(float4*)&Bs[k1][og * 4]     = bv0;
            *(float4*)&Bs[k1 + 8][og * 4] = bv1;
            __syncthreads();
#pragma unroll
            for (int k = 0; k < 16; k++) {
                float4 a  = *(const float4*)&As[k][tr * 4];
                float4 b0 = *(const float4*)&Bs[k][tc * 8];
                float4 b1 = *(const float4*)&Bs[k][tc * 8 + 4];
                float ar[4] = {a.x, a.y, a.z, a.w};
                float brv[8] = {b0.x, b0.y, b0.z, b0.w, b1.x, b1.y, b1.z, b1.w};
#pragma unroll
                for (int u = 0; u < 4; u++)
#pragma unroll
                    for (int v = 0; v < 8; v++) acc[u][v] = fmaf(ar[u], brv[v], acc[u][v]);
            }
        }
    }
    float* pp = g_part + ((size_t)(rs * BB + b) * NN + i0 + tr * 4) * OD + tc * 8;
#pragma unroll
    for (int u = 0; u < 4; u++) {
        float4 s0, s1;
        s0.x = acc[u][0]; s0.y = acc[u][1]; s0.z = acc[u][2]; s0.w = acc[u][3];
        s1.x = acc[u][4]; s1.y = acc[u][5]; s1.z = acc[u][6]; s1.w = acc[u][7];
        *(float4*)(pp + (size_t)u * OD)     = s0;
        *(float4*)(pp + (size_t)u * OD + 4) = s1;
    }
}

// ---------------------------------------------------------------------------
// Kernel 5: reduce r-splits, add bias, sigmoid. grid 512, block 256 (float4 per thread)
// ---------------------------------------------------------------------------
__global__ void k_sig(const float* __restrict__ bias, float* __restrict__ out) {
    int idx = blockIdx.x * blockDim.x + threadIdx.x;   // float4 index over B*N*OD/4
    const size_t stride4 = (size_t)BB * NN * OD / 4;
    const float4* p = (const float4*)g_part;
    float4 s0 = p[idx];
    float4 s1 = p[idx + stride4];
    float4 s2 = p[idx + 2 * stride4];
    float4 s3 = p[idx + 3 * stride4];
    int o4 = idx & (OD / 4 - 1);
    float4 bv = ((const float4*)bias)[o4];
    float x0 = s0.x + s1.x + s2.x + s3.x + bv.x;
    float x1 = s0.y + s1.y + s2.y + s3.y + bv.y;
    float x2 = s0.z + s1.z + s2.z + s3.z + bv.z;
    float x3 = s0.w + s1.w + s2.w + s3.w + bv.w;
    float4 o;
    o.x = 1.0f / (1.0f + expf(-x0));
    o.y = 1.0f / (1.0f + expf(-x1));
    o.z = 1.0f / (1.0f + expf(-x2));
    o.w = 1.0f / (1.0f + expf(-x3));
    ((float4*)out)[idx] = o;
}

// ---------------------------------------------------------------------------
extern "C" void kernel_launch(void* const* d_in, const int* in_sizes, int n_in,
                              void* d_out, int out_size) {
    const float* node = (const float*)d_in[0];   // (B,N,DE)
    const float* rel  = (const float*)d_in[1];   // (B,R,DR)
    const float* adj  = (const float*)d_in[2];   // (B,R,N,N)
    const float* Wb   = (const float*)d_in[3];   // (NBASE, FF)
    const float* Ww   = (const float*)d_in[4];   // (OD, NBASE)
    const float* bias = (const float*)d_in[5];   // (OD)
    float* out = (float*)d_out;                  // (B,N,OD)

    k_W   <<<dim3(FF / 256, OD / 8), 256>>>(Wb, Ww);
    k_c   <<<BB * RR, OD>>>(rel);
    k_Q   <<<dim3(NN / 64, BB * RR), 256>>>(node);
    k_main<<<dim3(NN / 64, BB, RSPLIT), 256>>>(adj);
    k_sig <<<(BB * NN * OD / 4) / 256, 256>>>(bias, out);
}

// round 8
// speedup vs baseline: 3.1207x; 3.1207x over previous
#include <cuda_runtime.h>
#include <math.h>
#include <stdint.h>

// Problem constants
#define BB 4
#define NN 1024
#define RR 16
#define DE 128
#define DR 64
#define NBASE 192
#define OD 128
#define FR (DE + DR)
#define FF (FR * RR)
#define RSPLIT 4
#define RG (RR / RSPLIT)

// main-GEMM tiling (mma.sync tf32)
#define TM 128
#define TN 128
#define BK 32
#define STAGES 4
#define CHUNKS (RG * NN / BK)          // 128 k-chunks per CTA
#define ASTRIDE 36                     // floats per SMEM row (pad 32->36: conflict-free)
#define STAGE_FLOATS (2 * 128 * ASTRIDE)   // A tile + B tile per stage
#define SMEM_TOTAL (STAGES * STAGE_FLOATS * 4)

// Scratch (explicitly aligned: cp.async/float4 paths require 16B alignment)
__device__ __align__(256) float g_WnT[RR * DE * OD];                 // [r][d][o]
__device__ __align__(256) float g_WrT[RR * DR * OD];                 // [r][e][o]
__device__ __align__(256) float g_c[BB * RR * OD];
__device__ __align__(256) float g_Q[(size_t)BB * RR * OD * NN];      // TRANSPOSED: [br][o][j], tf32-rounded
__device__ __align__(256) float g_part[(size_t)RSPLIT * BB * NN * OD];

// ---------------------------------------------------------------------------
// helpers
// ---------------------------------------------------------------------------
__device__ __forceinline__ uint32_t smem_u32(const void* p) {
    uint32_t a;
    asm("{ .reg .u64 t; cvta.to.shared.u64 t, %1; cvt.u32.u64 %0, t; }" : "=r"(a) : "l"(p));
    return a;
}
__device__ __forceinline__ void cp_async16(uint32_t dst, const void* src) {
    asm volatile("cp.async.cg.shared.global [%0], [%1], 16;" :: "r"(dst), "l"(src) : "memory");
}
__device__ __forceinline__ void cp_commit() {
    asm volatile("cp.async.commit_group;" ::: "memory");
}
__device__ __forceinline__ void cp_wait2() {
    asm volatile("cp.async.wait_group 2;" ::: "memory");
}
__device__ __forceinline__ uint32_t f2tf32(float x) {
    uint32_t u;
    asm("cvt.rna.tf32.f32 %0, %1;" : "=r"(u) : "f"(x));
    return u;
}
__device__ __forceinline__ float f2tf32f(float x) { return __uint_as_float(f2tf32(x)); }
__device__ __forceinline__ void mma_tf32(float* c, const uint32_t* a, const uint32_t* b) {
    asm volatile(
        "mma.sync.aligned.m16n8k8.row.col.f32.tf32.tf32.f32 "
        "{%0,%1,%2,%3}, {%4,%5,%6,%7}, {%8,%9}, {%0,%1,%2,%3};"
        : "+f"(c[0]), "+f"(c[1]), "+f"(c[2]), "+f"(c[3])
        : "r"(a[0]), "r"(a[1]), "r"(a[2]), "r"(a[3]), "r"(b[0]), "r"(b[1]));
}

// ---------------------------------------------------------------------------
// Kernel 1: W = Ww @ Wb (node part -> g_WnT [r][d][o], rel part -> g_WrT)
// ---------------------------------------------------------------------------
__global__ void k_W(const float* __restrict__ Wb, const float* __restrict__ Ww) {
    __shared__ float sWw[8][NBASE];
    int tx = threadIdx.x;
    int f  = blockIdx.x * 256 + tx;
    int o0 = blockIdx.y * 8;
    for (int i = tx; i < 8 * NBASE; i += 256)
        sWw[i / NBASE][i % NBASE] = Ww[(o0 + i / NBASE) * NBASE + (i % NBASE)];
    __syncthreads();
    float acc[8];
#pragma unroll
    for (int oo = 0; oo < 8; oo++) acc[oo] = 0.f;
    for (int m = 0; m < NBASE; m++) {
        float wb = Wb[m * FF + f];
#pragma unroll
        for (int oo = 0; oo < 8; oo++) acc[oo] = fmaf(sWw[oo][m], wb, acc[oo]);
    }
    int r = f / FR, d = f % FR;
    if (d < DE) {
#pragma unroll
        for (int oo = 0; oo < 8; oo++) g_WnT[(r * DE + d) * OD + o0 + oo] = acc[oo];
    } else {
        int e = d - DE;
#pragma unroll
        for (int oo = 0; oo < 8; oo++) g_WrT[(r * DR + e) * OD + o0 + oo] = acc[oo];
    }
}

// ---------------------------------------------------------------------------
// Kernel 2: c[b,r,o] = sum_e rel[b,r,e] * WrT[r][e][o]
// ---------------------------------------------------------------------------
__global__ void k_c(const float* __restrict__ rel) {
    int br = blockIdx.x;
    int r  = br % RR;
    int o  = threadIdx.x;
    float s = 0.f;
    const float* rp = rel + br * DR;
    const float* wp = g_WrT + r * DR * OD + o;
#pragma unroll 8
    for (int e = 0; e < DR; e++) s = fmaf(rp[e], wp[e * OD], s);
    g_c[br * OD + o] = s;
}

// ---------------------------------------------------------------------------
// Kernel 3: Q'[br][o][j] = tf32( (node_b @ WnT_r)[j,o] + c[b,r,o] )   transposed
// ---------------------------------------------------------------------------
__global__ void __launch_bounds__(256, 2) k_Q(const float* __restrict__ node) {
    __shared__ float As[16][68];
    __shared__ float Bs[16][128];
    int tx = threadIdx.x;
    int tr = tx >> 4;
    int tc = tx & 15;
    int j0 = blockIdx.x * 64;
    int br = blockIdx.y;
    int b = br / RR, r = br % RR;
    int arow = tx >> 2;
    int aq   = tx & 3;

    const float* nodeBase = node + ((size_t)b * NN + j0) * DE;
    const float* wBase    = g_WnT + (size_t)r * DE * OD;

    float acc[4][8];
#pragma unroll
    for (int u = 0; u < 4; u++)
#pragma unroll
        for (int v = 0; v < 8; v++) acc[u][v] = 0.f;

    for (int d0 = 0; d0 < DE; d0 += 16) {
        float4 av  = *(const float4*)(nodeBase + (size_t)arow * DE + d0 + aq * 4);
        int k1 = tx >> 5, og = tx & 31;
        float4 bv0 = *(const float4*)(wBase + (size_t)(d0 + k1)     * OD + og * 4);
        float4 bv1 = *(const float4*)(wBase + (size_t)(d0 + k1 + 8) * OD + og * 4);
        __syncthreads();
        As[aq * 4 + 0][arow] = av.x;
        As[aq * 4 + 1][arow] = av.y;
        As[aq * 4 + 2][arow] = av.z;
        As[aq * 4 + 3][arow] = av.w;
        *(float4*)&Bs[k1][og * 4]     = bv0;
        *(float4*)&Bs[k1 + 8][og * 4] = bv1;
        __syncthreads();
#pragma unroll
        for (int k = 0; k < 16; k++) {
            float4 a  = *(const float4*)&As[k][tr * 4];
            float4 b0 = *(const float4*)&Bs[k][tc * 8];
            float4 b1 = *(const float4*)&Bs[k][tc * 8 + 4];
            float ar[4] = {a.x, a.y, a.z, a.w};
            float brv[8] = {b0.x, b0.y, b0.z, b0.w, b1.x, b1.y, b1.z, b1.w};
#pragma unroll
            for (int u = 0; u < 4; u++)
#pragma unroll
                for (int v = 0; v < 8; v++) acc[u][v] = fmaf(ar[u], brv[v], acc[u][v]);
        }
    }
    float4 c0 = *(const float4*)(g_c + br * OD + tc * 8);
    float4 c1 = *(const float4*)(g_c + br * OD + tc * 8 + 4);
    float cv[8] = {c0.x, c0.y, c0.z, c0.w, c1.x, c1.y, c1.z, c1.w};
#pragma unroll
    for (int v = 0; v < 8; v++) {
        int o = tc * 8 + v;
        float4 s;
        s.x = f2tf32f(acc[0][v] + cv[v]);
        s.y = f2tf32f(acc[1][v] + cv[v]);
        s.z = f2tf32f(acc[2][v] + cv[v]);
        s.w = f2tf32f(acc[3][v] + cv[v]);
        *(float4*)(g_Q + ((size_t)br * OD + o) * NN + j0 + tr * 4) = s;
    }
}

// ---------------------------------------------------------------------------
// Kernel 4: mma.sync tf32 main GEMM.
// part[rs][b][i][o] = sum_{r in split} sum_j adj[b,r,i,j] * Qt[b,r,o,j]
// grid (8, BB, RSPLIT) = 128 CTAs, block 256 (8 warps, 4x2 layout, 32x64 warp tile)
// ---------------------------------------------------------------------------
__device__ __forceinline__ void load_stage(const float* adj, int b, int rs, int i0,
                                           int kc, uint32_t sb, int tid) {
    int s  = kc & (STAGES - 1);
    int r  = rs * RG + (kc >> 5);
    int j0 = (kc & 31) * BK;
    const float* aB = adj + ((size_t)(b * RR + r) * NN + i0) * NN + j0;
    const float* qB = g_Q + ((size_t)(b * RR + r) * OD) * NN + j0;
    uint32_t sA = sb + s * (STAGE_FLOATS * 4);
    uint32_t sB = sA + 128 * ASTRIDE * 4;
#pragma unroll
    for (int it = 0; it < 4; it++) {
        int ch = tid + it * 256;                 // 1024 16B ops for A
        int row = ch >> 3, c16 = ch & 7;
        cp_async16(sA + row * (ASTRIDE * 4) + c16 * 16, aB + (size_t)row * NN + c16 * 4);
    }
#pragma unroll
    for (int it = 0; it < 4; it++) {
        int ch = tid + it * 256;                 // 1024 16B ops for B
        int row = ch >> 3, c16 = ch & 7;
        cp_async16(sB + row * (ASTRIDE * 4) + c16 * 16, qB + (size_t)row * NN + c16 * 4);
    }
    cp_commit();
}

__global__ void __launch_bounds__(256, 1) k_main_mma(const float* __restrict__ adj) {
    extern __shared__ float sm[];
    uint32_t sb = smem_u32(sm);
    int tid  = threadIdx.x;
    int wid  = tid >> 5;
    int lane = tid & 31;
    int g    = lane >> 2;        // 0..7
    int tig  = lane & 3;         // 0..3
    int wm   = wid & 3;          // 4 m-groups of 32 rows
    int wn   = wid >> 2;         // 2 n-groups of 64 cols
    int i0 = blockIdx.x * TM;
    int b  = blockIdx.y;
    int rs = blockIdx.z;

    float c[2][8][4];
#pragma unroll
    for (int mt = 0; mt < 2; mt++)
#pragma unroll
        for (int nt = 0; nt < 8; nt++)
#pragma unroll
            for (int q = 0; q < 4; q++) c[mt][nt][q] = 0.f;

    // prologue: fill STAGES-1 stages
#pragma unroll
    for (int kc = 0; kc < STAGES - 1; kc++) load_stage(adj, b, rs, i0, kc, sb, tid);

    const uint32_t* smu = (const uint32_t*)sm;

    for (int kc = 0; kc < CHUNKS; kc++) {
        cp_wait2();
        __syncthreads();
        int s = kc & (STAGES - 1);
        const float*    sA = sm  + s * STAGE_FLOATS;
        const uint32_t* sB = smu + s * STAGE_FLOATS + 128 * ASTRIDE;
#pragma unroll
        for (int ks = 0; ks < 4; ks++) {
            int k0 = ks * 8;
            uint32_t af[2][4];
#pragma unroll
            for (int mt = 0; mt < 2; mt++) {
                int row = wm * 32 + mt * 16 + g;
                af[mt][0] = f2tf32(sA[row * ASTRIDE + k0 + tig]);
                af[mt][1] = f2tf32(sA[(row + 8) * ASTRIDE + k0 + tig]);
                af[mt][2] = f2tf32(sA[row * ASTRIDE + k0 + tig + 4]);
                af[mt][3] = f2tf32(sA[(row + 8) * ASTRIDE + k0 + tig + 4]);
            }
            uint32_t bf[8][2];
#pragma unroll
            for (int nt = 0; nt < 8; nt++) {
                int n = wn * 64 + nt * 8 + g;
                bf[nt][0] = sB[n * ASTRIDE + k0 + tig];
                bf[nt][1] = sB[n * ASTRIDE + k0 + tig + 4];
            }
#pragma unroll
            for (int mt = 0; mt < 2; mt++)
#pragma unroll
                for (int nt = 0; nt < 8; nt++)
                    mma_tf32(c[mt][nt], af[mt], bf[nt]);
        }
        __syncthreads();
        if (kc + STAGES - 1 < CHUNKS)
            load_stage(adj, b, rs, i0, kc + STAGES - 1, sb, tid);
    }

    // epilogue: store accumulators
    float* pbase = g_part + (size_t)(rs * BB + b) * NN * OD;
#pragma unroll
    for (int mt = 0; mt < 2; mt++) {
        int row = i0 + wm * 32 + mt * 16 + g;
#pragma unroll
        for (int nt = 0; nt < 8; nt++) {
            int col = wn * 64 + nt * 8 + tig * 2;
            float2 lo = make_float2(c[mt][nt][0], c[mt][nt][1]);
            float2 hi = make_float2(c[mt][nt][2], c[mt][nt][3]);
            *(float2*)(pbase + (size_t)row * OD + col)       = lo;
            *(float2*)(pbase + (size_t)(row + 8) * OD + col) = hi;
        }
    }
}

// ---------------------------------------------------------------------------
// Kernel 5: reduce r-splits, add bias, sigmoid.
// ---------------------------------------------------------------------------
__global__ void k_sig(const float* __restrict__ bias, float* __restrict__ out) {
    int idx = blockIdx.x * blockDim.x + threadIdx.x;
    const size_t stride4 = (size_t)BB * NN * OD / 4;
    const float4* p = (const float4*)g_part;
    float4 s0 = p[idx];
    float4 s1 = p[idx + stride4];
    float4 s2 = p[idx + 2 * stride4];
    float4 s3 = p[idx + 3 * stride4];
    int o4 = idx & (OD / 4 - 1);
    float4 bv = ((const float4*)bias)[o4];
    float x0 = s0.x + s1.x + s2.x + s3.x + bv.x;
    float x1 = s0.y + s1.y + s2.y + s3.y + bv.y;
    float x2 = s0.z + s1.z + s2.z + s3.z + bv.z;
    float x3 = s0.w + s1.w + s2.w + s3.w + bv.w;
    float4 o;
    o.x = 1.0f / (1.0f + expf(-x0));
    o.y = 1.0f / (1.0f + expf(-x1));
    o.z = 1.0f / (1.0f + expf(-x2));
    o.w = 1.0f / (1.0f + expf(-x3));
    ((float4*)out)[idx] = o;
}

// ---------------------------------------------------------------------------
extern "C" void kernel_launch(void* const* d_in, const int* in_sizes, int n_in,
                              void* d_out, int out_size) {
    const float* node = (const float*)d_in[0];
    const float* rel  = (const float*)d_in[1];
    const float* adj  = (const float*)d_in[2];
    const float* Wb   = (const float*)d_in[3];
    const float* Ww   = (const float*)d_in[4];
    const float* bias = (const float*)d_in[5];
    float* out = (float*)d_out;

    cudaFuncSetAttribute(k_main_mma, cudaFuncAttributeMaxDynamicSharedMemorySize, SMEM_TOTAL);

    k_W   <<<dim3(FF / 256, OD / 8), 256>>>(Wb, Ww);
    k_c   <<<BB * RR, OD>>>(rel);
    k_Q   <<<dim3(NN / 64, BB * RR), 256>>>(node);
    k_main_mma<<<dim3(NN / TM, BB, RSPLIT), 256, SMEM_TOTAL>>>(adj);
    k_sig <<<(BB * NN * OD / 4) / 256, 256>>>(bias, out);
}

// round 9
// speedup vs baseline: 4.2750x; 1.3699x over previous
#include <cuda_runtime.h>
#include <math.h>
#include <stdint.h>

// Problem constants
#define BB 4
#define NN 1024
#define RR 16
#define DE 128
#define DR 64
#define NBASE 192
#define OD 128
#define FR (DE + DR)
#define FF (FR * RR)
#define RSPLIT 8
#define RG (RR / RSPLIT)               // 2 relations per main CTA

// mma GEMM tiling (shared by k_main_mma and k_Q_mma)
#define TM 128
#define TN 128
#define BK 32
#define CHUNKS (RG * NN / BK)          // 64 k-chunks per main CTA
#define QCHUNKS (DE / BK)              // 4 k-chunks per Q CTA
#define ASTRIDE 36                     // floats per SMEM row (pad 32->36: conflict-free)
#define STAGE_FLOATS (2 * 128 * ASTRIDE)   // A tile + B tile per stage
#define SMEM_PIPE (2 * STAGE_FLOATS * 4)   // 2 stages = 73728 B -> 2 CTAs/SM

// Scratch (aligned for cp.async / float4)
__device__ __align__(256) float g_Wn[RR * OD * DE];                  // [r][o][d]  (K-major A for k_Q_mma)
__device__ __align__(256) float g_WrT[RR * DR * OD];                 // [r][e][o]
__device__ __align__(256) float g_c[BB * RR * OD];
__device__ __align__(256) float g_Q[(size_t)BB * RR * OD * NN];      // [br][o][j], tf32-rounded
__device__ __align__(256) float g_part[(size_t)RSPLIT * BB * NN * OD];  // 16 MB

// ---------------------------------------------------------------------------
// helpers
// ---------------------------------------------------------------------------
__device__ __forceinline__ uint32_t smem_u32(const void* p) {
    uint32_t a;
    asm("{ .reg .u64 t; cvta.to.shared.u64 t, %1; cvt.u32.u64 %0, t; }" : "=r"(a) : "l"(p));
    return a;
}
__device__ __forceinline__ void cp_async16(uint32_t dst, const void* src) {
    asm volatile("cp.async.cg.shared.global [%0], [%1], 16;" :: "r"(dst), "l"(src) : "memory");
}
__device__ __forceinline__ void cp_commit() {
    asm volatile("cp.async.commit_group;" ::: "memory");
}
__device__ __forceinline__ void cp_wait1() {
    asm volatile("cp.async.wait_group 1;" ::: "memory");
}
__device__ __forceinline__ void cp_wait0() {
    asm volatile("cp.async.wait_group 0;" ::: "memory");
}
__device__ __forceinline__ uint32_t f2tf32(float x) {
    uint32_t u;
    asm("cvt.rna.tf32.f32 %0, %1;" : "=r"(u) : "f"(x));
    return u;
}
__device__ __forceinline__ float f2tf32f(float x) { return __uint_as_float(f2tf32(x)); }
__device__ __forceinline__ void mma_tf32(float* c, const uint32_t* a, const uint32_t* b) {
    asm volatile(
        "mma.sync.aligned.m16n8k8.row.col.f32.tf32.tf32.f32 "
        "{%0,%1,%2,%3}, {%4,%5,%6,%7}, {%8,%9}, {%0,%1,%2,%3};"
        : "+f"(c[0]), "+f"(c[1]), "+f"(c[2]), "+f"(c[3])
        : "r"(a[0]), "r"(a[1]), "r"(a[2]), "r"(a[3]), "r"(b[0]), "r"(b[1]));
}

// generic stage loader: A rows [0,128) stride strideA, B rows [0,128) stride strideB
__device__ __forceinline__ void pipe_load(const float* aB, size_t strideA,
                                          const float* bB, size_t strideB,
                                          uint32_t sb, int s, int tid) {
    uint32_t sA = sb + s * (STAGE_FLOATS * 4);
    uint32_t sB = sA + 128 * ASTRIDE * 4;
#pragma unroll
    for (int it = 0; it < 4; it++) {
        int ch = tid + it * 256;
        int row = ch >> 3, c16 = ch & 7;
        cp_async16(sA + row * (ASTRIDE * 4) + c16 * 16, aB + (size_t)row * strideA + c16 * 4);
    }
#pragma unroll
    for (int it = 0; it < 4; it++) {
        int ch = tid + it * 256;
        int row = ch >> 3, c16 = ch & 7;
        cp_async16(sB + row * (ASTRIDE * 4) + c16 * 16, bB + (size_t)row * strideB + c16 * 4);
    }
    cp_commit();
}

// ---------------------------------------------------------------------------
// Kernel 1: W = Ww @ Wb.  Node part stored K-major [r][o][d]; rel part [r][e][o].
// ---------------------------------------------------------------------------
__global__ void k_W(const float* __restrict__ Wb, const float* __restrict__ Ww) {
    __shared__ float sWw[8][NBASE];
    int tx = threadIdx.x;
    int f  = blockIdx.x * 256 + tx;
    int o0 = blockIdx.y * 8;
    for (int i = tx; i < 8 * NBASE; i += 256)
        sWw[i / NBASE][i % NBASE] = Ww[(o0 + i / NBASE) * NBASE + (i % NBASE)];
    __syncthreads();
    float acc[8];
#pragma unroll
    for (int oo = 0; oo < 8; oo++) acc[oo] = 0.f;
    for (int m = 0; m < NBASE; m++) {
        float wb = Wb[m * FF + f];
#pragma unroll
        for (int oo = 0; oo < 8; oo++) acc[oo] = fmaf(sWw[oo][m], wb, acc[oo]);
    }
    int r = f / FR, d = f % FR;
    if (d < DE) {
#pragma unroll
        for (int oo = 0; oo < 8; oo++) g_Wn[((size_t)r * OD + o0 + oo) * DE + d] = acc[oo];
    } else {
        int e = d - DE;
#pragma unroll
        for (int oo = 0; oo < 8; oo++) g_WrT[(r * DR + e) * OD + o0 + oo] = acc[oo];
    }
}

// ---------------------------------------------------------------------------
// Kernel 2: c[b,r,o] = sum_e rel[b,r,e] * WrT[r][e][o]
// ---------------------------------------------------------------------------
__global__ void k_c(const float* __restrict__ rel) {
    int br = blockIdx.x;
    int r  = br % RR;
    int o  = threadIdx.x;
    float s = 0.f;
    const float* rp = rel + br * DR;
    const float* wp = g_WrT + r * DR * OD + o;
#pragma unroll 8
    for (int e = 0; e < DR; e++) s = fmaf(rp[e], wp[e * OD], s);
    g_c[br * OD + o] = s;
}

// ---------------------------------------------------------------------------
// Kernel 3: Q[br][o][j] = tf32( Wn_r[o][:] . node_b[j][:] + c[b,r,o] )
// mma.sync tf32.  grid (NN/TN=8, BB*RR=64), block 256 (8 warps, 4x2, 32x64 tile)
// ---------------------------------------------------------------------------
__global__ void __launch_bounds__(256, 2) k_Q_mma(const float* __restrict__ node) {
    extern __shared__ float sm[];
    uint32_t sb = smem_u32(sm);
    int tid  = threadIdx.x;
    int wid  = tid >> 5;
    int lane = tid & 31;
    int g    = lane >> 2;
    int tig  = lane & 3;
    int wm   = wid & 3;
    int wn   = wid >> 2;
    int j0 = blockIdx.x * TN;
    int br = blockIdx.y;
    int b = br / RR, r = br % RR;

    const float* aBase = g_Wn + (size_t)r * OD * DE;         // [o][d]
    const float* bBase = node + ((size_t)b * NN + j0) * DE;  // [j][d]

    float c[2][8][4];
#pragma unroll
    for (int mt = 0; mt < 2; mt++)
#pragma unroll
        for (int nt = 0; nt < 8; nt++)
#pragma unroll
            for (int q = 0; q < 4; q++) c[mt][nt][q] = 0.f;

    pipe_load(aBase, DE, bBase, DE, sb, 0, tid);

    const float*    smf = sm;
    const float*    dummy;
    (void)dummy;

    for (int kc = 0; kc < QCHUNKS; kc++) {
        if (kc + 1 < QCHUNKS) {
            pipe_load(aBase + (kc + 1) * BK, DE, bBase + (kc + 1) * BK, DE, sb, (kc + 1) & 1, tid);
            cp_wait1();
        } else {
            cp_wait0();
        }
        __syncthreads();
        int s = kc & 1;
        const float* sA = smf + s * STAGE_FLOATS;
        const float* sB = smf + s * STAGE_FLOATS + 128 * ASTRIDE;
#pragma unroll
        for (int ks = 0; ks < 4; ks++) {
            int k0 = ks * 8;
            uint32_t af[2][4];
#pragma unroll
            for (int mt = 0; mt < 2; mt++) {
                int row = wm * 32 + mt * 16 + g;
                af[mt][0] = f2tf32(sA[row * ASTRIDE + k0 + tig]);
                af[mt][1] = f2tf32(sA[(row + 8) * ASTRIDE + k0 + tig]);
                af[mt][2] = f2tf32(sA[row * ASTRIDE + k0 + tig + 4]);
                af[mt][3] = f2tf32(sA[(row + 8) * ASTRIDE + k0 + tig + 4]);
            }
            uint32_t bf[8][2];
#pragma unroll
            for (int nt = 0; nt < 8; nt++) {
                int n = wn * 64 + nt * 8 + g;
                bf[nt][0] = f2tf32(sB[n * ASTRIDE + k0 + tig]);
                bf[nt][1] = f2tf32(sB[n * ASTRIDE + k0 + tig + 4]);
            }
#pragma unroll
            for (int mt = 0; mt < 2; mt++)
#pragma unroll
                for (int nt = 0; nt < 8; nt++)
                    mma_tf32(c[mt][nt], af[mt], bf[nt]);
        }
        __syncthreads();
    }

    // epilogue: +c[b,r,o], round to tf32, store transposed Q[o][j]
    float* qbase = g_Q + (size_t)br * OD * NN;
#pragma unroll
    for (int mt = 0; mt < 2; mt++) {
        int row = wm * 32 + mt * 16 + g;
        float cv0 = g_c[br * OD + row];
        float cv1 = g_c[br * OD + row + 8];
#pragma unroll
        for (int nt = 0; nt < 8; nt++) {
            int col = j0 + wn * 64 + nt * 8 + tig * 2;
            float2 lo = make_float2(f2tf32f(c[mt][nt][0] + cv0), f2tf32f(c[mt][nt][1] + cv0));
            float2 hi = make_float2(f2tf32f(c[mt][nt][2] + cv1), f2tf32f(c[mt][nt][3] + cv1));
            *(float2*)(qbase + (size_t)row * NN + col)       = lo;
            *(float2*)(qbase + (size_t)(row + 8) * NN + col) = hi;
        }
    }
}

// ---------------------------------------------------------------------------
// Kernel 4: mma.sync tf32 main GEMM.
// part[rs][b][i][o] = sum_{r in split} sum_j adj[b,r,i,j] * Q[b,r,o,j]
// grid (8, BB, RSPLIT=8) = 256 CTAs -> 2 CTAs/SM.  block 256.
// ---------------------------------------------------------------------------
__global__ void __launch_bounds__(256, 2) k_main_mma(const float* __restrict__ adj) {
    extern __shared__ float sm[];
    uint32_t sb = smem_u32(sm);
    int tid  = threadIdx.x;
    int wid  = tid >> 5;
    int lane = tid & 31;
    int g    = lane >> 2;
    int tig  = lane & 3;
    int wm   = wid & 3;
    int wn   = wid >> 2;
    int i0 = blockIdx.x * TM;
    int b  = blockIdx.y;
    int rs = blockIdx.z;

    float c[2][8][4];
#pragma unroll
    for (int mt = 0; mt < 2; mt++)
#pragma unroll
        for (int nt = 0; nt < 8; nt++)
#pragma unroll
            for (int q = 0; q < 4; q++) c[mt][nt][q] = 0.f;

    // chunk kc: r = rs*RG + (kc>>5), j0 = (kc&31)*BK
    {
        int r = rs * RG;
        pipe_load(adj + ((size_t)(b * RR + r) * NN + i0) * NN, NN,
                  g_Q + (size_t)(b * RR + r) * OD * NN, NN, sb, 0, tid);
    }

    const float* smf = sm;

    for (int kc = 0; kc < CHUNKS; kc++) {
        if (kc + 1 < CHUNKS) {
            int kn = kc + 1;
            int r  = rs * RG + (kn >> 5);
            int j0 = (kn & 31) * BK;
            pipe_load(adj + ((size_t)(b * RR + r) * NN + i0) * NN + j0, NN,
                      g_Q + (size_t)(b * RR + r) * OD * NN + j0, NN, sb, kn & 1, tid);
            cp_wait1();
        } else {
            cp_wait0();
        }
        __syncthreads();
        int s = kc & 1;
        const float* sA = smf + s * STAGE_FLOATS;
        const float* sB = smf + s * STAGE_FLOATS + 128 * ASTRIDE;
#pragma unroll
        for (int ks = 0; ks < 4; ks++) {
            int k0 = ks * 8;
            uint32_t af[2][4];
#pragma unroll
            for (int mt = 0; mt < 2; mt++) {
                int row = wm * 32 + mt * 16 + g;
                af[mt][0] = f2tf32(sA[row * ASTRIDE + k0 + tig]);
                af[mt][1] = f2tf32(sA[(row + 8) * ASTRIDE + k0 + tig]);
                af[mt][2] = f2tf32(sA[row * ASTRIDE + k0 + tig + 4]);
                af[mt][3] = f2tf32(sA[(row + 8) * ASTRIDE + k0 + tig + 4]);
            }
            uint32_t bf[8][2];
#pragma unroll
            for (int nt = 0; nt < 8; nt++) {
                int n = wn * 64 + nt * 8 + g;
                bf[nt][0] = __float_as_uint(sB[n * ASTRIDE + k0 + tig]);
                bf[nt][1] = __float_as_uint(sB[n * ASTRIDE + k0 + tig + 4]);
            }
#pragma unroll
            for (int mt = 0; mt < 2; mt++)
#pragma unroll
                for (int nt = 0; nt < 8; nt++)
                    mma_tf32(c[mt][nt], af[mt], bf[nt]);
        }
        __syncthreads();
    }

    float* pbase = g_part + (size_t)(rs * BB + b) * NN * OD;
#pragma unroll
    for (int mt = 0; mt < 2; mt++) {
        int row = i0 + wm * 32 + mt * 16 + g;
#pragma unroll
        for (int nt = 0; nt < 8; nt++) {
            int col = wn * 64 + nt * 8 + tig * 2;
            float2 lo = make_float2(c[mt][nt][0], c[mt][nt][1]);
            float2 hi = make_float2(c[mt][nt][2], c[mt][nt][3]);
            *(float2*)(pbase + (size_t)row * OD + col)       = lo;
            *(float2*)(pbase + (size_t)(row + 8) * OD + col) = hi;
        }
    }
}

// ---------------------------------------------------------------------------
// Kernel 5: reduce 8 r-splits, add bias, sigmoid.
// ---------------------------------------------------------------------------
__global__ void k_sig(const float* __restrict__ bias, float* __restrict__ out) {
    int idx = blockIdx.x * blockDim.x + threadIdx.x;
    const size_t stride4 = (size_t)BB * NN * OD / 4;
    const float4* p = (const float4*)g_part;
    float x0 = 0.f, x1 = 0.f, x2 = 0.f, x3 = 0.f;
#pragma unroll
    for (int s = 0; s < RSPLIT; s++) {
        float4 v = p[idx + s * stride4];
        x0 += v.x; x1 += v.y; x2 += v.z; x3 += v.w;
    }
    int o4 = idx & (OD / 4 - 1);
    float4 bv = ((const float4*)bias)[o4];
    x0 += bv.x; x1 += bv.y; x2 += bv.z; x3 += bv.w;
    float4 o;
    o.x = 1.0f / (1.0f + expf(-x0));
    o.y = 1.0f / (1.0f + expf(-x1));
    o.z = 1.0f / (1.0f + expf(-x2));
    o.w = 1.0f / (1.0f + expf(-x3));
    ((float4*)out)[idx] = o;
}

// ---------------------------------------------------------------------------
extern "C" void kernel_launch(void* const* d_in, const int* in_sizes, int n_in,
                              void* d_out, int out_size) {
    const float* node = (const float*)d_in[0];
    const float* rel  = (const float*)d_in[1];
    const float* adj  = (const float*)d_in[2];
    const float* Wb   = (const float*)d_in[3];
    const float* Ww   = (const float*)d_in[4];
    const float* bias = (const float*)d_in[5];
    float* out = (float*)d_out;

    cudaFuncSetAttribute(k_main_mma, cudaFuncAttributeMaxDynamicSharedMemorySize, SMEM_PIPE);
    cudaFuncSetAttribute(k_Q_mma,    cudaFuncAttributeMaxDynamicSharedMemorySize, SMEM_PIPE);

    k_W      <<<dim3(FF / 256, OD / 8), 256>>>(Wb, Ww);
    k_c      <<<BB * RR, OD>>>(rel);
    k_Q_mma  <<<dim3(NN / TN, BB * RR), 256, SMEM_PIPE>>>(node);
    k_main_mma<<<dim3(NN / TM, BB, RSPLIT), 256, SMEM_PIPE>>>(adj);
    k_sig    <<<(BB * NN * OD / 4) / 256, 256>>>(bias, out);
}